// round 13
// baseline (speedup 1.0000x reference)
#include <cuda_runtime.h>
#include <cstdint>
#include <cstddef>

#define CH   40
#define TT   2000
#define LL   256
#define NB   64
#define NEGF (-1.0e30f)
#define POSF (1.0e30f)
#define LOG2E 1.4426950408889634f
#define LN2   0.6931471805599453f

// lg2(1+u) ~ poly(x), x = u-1, u in [0,2]
#define D0 0.999835f
#define D1 0.721619f
#define D2 (-0.177414f)
#define D3 0.058070f
#define D4 (-0.029748f)
#define D5 0.0127536f

// ---------------- device scratch ----------------
__device__ unsigned long long g_maskkeys[NB * 256];
__device__ int   g_labels[NB * 256];
__device__ int   g_tlen[NB];
__device__ float g_em[(size_t)NB * TT * 256];
__device__ float g_loss[NB];
__device__ unsigned int g_done;

// ---------------- PTX helpers ----------------
__device__ __forceinline__ float ex2f(float x) {
    float r; asm("ex2.approx.ftz.f32 %0, %1;" : "=f"(r) : "f"(x)); return r;
}
__device__ __forceinline__ float lg2f(float x) {
    float r; asm("lg2.approx.ftz.f32 %0, %1;" : "=f"(r) : "f"(x)); return r;
}
__device__ __forceinline__ unsigned long long pk2(float x, float y) {
    unsigned long long r;
    asm("mov.b64 %0, {%1, %2};" : "=l"(r) : "f"(x), "f"(y));
    return r;
}
__device__ __forceinline__ unsigned long long add2(unsigned long long a, unsigned long long b) {
    unsigned long long r;
    asm("add.rn.f32x2 %0, %1, %2;" : "=l"(r) : "l"(a), "l"(b));
    return r;
}
__device__ __forceinline__ void up2(unsigned long long v, float &x, float &y) {
    asm("mov.b64 {%0, %1}, %2;" : "=f"(x), "=f"(y) : "l"(v));
}

// =====================================================================
// Kernel 0: no-op (keeps ncu capture index on k_ctc)
// =====================================================================
__global__ void k_nop() {}

// =====================================================================
// Kernel 1: preprocessing (verified exact)
// =====================================================================
__global__ void k_preprocess(const int* __restrict__ targets) {
    const int n = blockIdx.x;
    const int l = threadIdx.x;

    __shared__ unsigned long long skey[256];
    __shared__ int sscan[256];
    __shared__ int sinv[256];

    if (n == 0 && l == 0) g_done = 0;

    unsigned long long key = 0ull;
#pragma unroll
    for (int c = 0; c < CH; c++) {
        key |= ((unsigned long long)(targets[(n * CH + c) * LL + l] & 1)) << (CH - 1 - c);
    }
    skey[l] = (key << 8) | (unsigned long long)l;
    __syncthreads();

    for (int k = 2; k <= 256; k <<= 1) {
        for (int j = k >> 1; j > 0; j >>= 1) {
            int ixj = l ^ j;
            if (ixj > l) {
                unsigned long long a = skey[l], b = skey[ixj];
                bool up = ((l & k) == 0);
                if ((a > b) == up) { skey[l] = b; skey[ixj] = a; }
            }
            __syncthreads();
        }
    }

    unsigned long long kv = skey[l] >> 8;
    unsigned long long kvp = (l > 0) ? (skey[l - 1] >> 8) : 0ull;
    int head = (l == 0 || kv != kvp) ? 1 : 0;
    sscan[l] = head;
    __syncthreads();
    for (int off = 1; off < 256; off <<= 1) {
        int v = sscan[l];
        int w = (l >= off) ? sscan[l - off] : 0;
        __syncthreads();
        sscan[l] = v + w;
        __syncthreads();
    }
    const int u   = sscan[255];
    const int uid = sscan[l] - 1;
    const int orig = (int)(skey[l] & 255ull);
    int inv2 = uid + 1; if (inv2 == u) inv2 = 0;
    sinv[orig] = inv2;
    if (head) g_maskkeys[n * 256 + inv2] = kv;
    __syncthreads();

    int flag = (l > 0 && sinv[l] != sinv[l - 1]) ? 1 : 0;
    int myinv = sinv[l];
    sscan[l] = flag;
    __syncthreads();
    for (int off = 1; off < 256; off <<= 1) {
        int v = sscan[l];
        int w = (l >= off) ? sscan[l - off] : 0;
        __syncthreads();
        sscan[l] = v + w;
        __syncthreads();
    }
    if (flag) g_labels[n * 256 + (sscan[l] - 1)] = myinv;
    if (l == 0) g_tlen[n] = sscan[255];
}

// =====================================================================
// Kernel 2: emission v4 — subset-sum decomposition.
// em[t][j] = base[t] + sum_{g=0}^{7} S[g][pattern_g(j)][t]
// S[g][p][t] built incrementally (1 add per entry); each j gathers its
// 8 group rows -> 8 packed adds per t-pair instead of 40 FFMA2s.
// =====================================================================
#define TTILE 32
#define SPAD  34   // even pad -> u64-aligned; gather banks spread (p+tp)%16
__global__ void __launch_bounds__(256) k_emission(const float* __restrict__ lp) {
    const int n  = blockIdx.y;
    const int t0 = blockIdx.x * TTILE;
    const int j  = threadIdx.x;          // 0..255

    __shared__ __align__(16) float S[8][32][SPAD];   // 34.8 KB
    __shared__ __align__(16) float d2f[CH][TTILE];   // 5.1 KB
    __shared__ __align__(8)  float sbase[TTILE];
    __shared__ float sblank[TTILE];

    const float* lp0 = lp + ((size_t)n * 2 + 0) * CH * TT;
    const float* lp1 = lp + ((size_t)n * 2 + 1) * CH * TT;

    // stage d2f: 1280 entries, 5 passes of 256 threads (coalesced over t)
#pragma unroll
    for (int it = 0; it < 5; it++) {
        int idx = it * 256 + j;
        int c = idx >> 5;
        int tt = idx & 31;
        int t = t0 + tt;
        float v = 0.0f;
        if (t < TT) {
            float x0 = __ldg(lp0 + c * TT + t);
            float x1 = __ldg(lp1 + c * TT + t);
            v = (x1 - x0) * LOG2E;
        }
        d2f[c][tt] = v;
    }
    // base + blank (threads 0..31)
    if (j < TTILE) {
        int t = t0 + j;
        float b = 0.0f, bl = 0.0f;
        if (t < TT) {
#pragma unroll
            for (int c = 0; c < CH; c++) b += __ldg(lp0 + c * TT + t);
            bl = __ldg(lp1 + t);
        }
        sbase[j]  = b * LOG2E;
        sblank[j] = bl * LOG2E;
    }
    __syncthreads();

    // build S: thread owns one (g, tt) column; 31 incremental adds.
    // pattern bit b <-> channel c = 5g + 4 - b  (mk bit 39-c)
    {
        int g = j >> 5;
        int tt = j & 31;
        S[g][0][tt] = 0.0f;
#pragma unroll 1
        for (int p = 1; p < 32; p++) {
            int b = __ffs(p) - 1;
            int c = 5 * g + 4 - b;
            S[g][p][tt] = S[g][p & (p - 1)][tt] + d2f[c][tt];
        }
    }
    __syncthreads();

    // per-j group patterns
    const unsigned long long mk = g_maskkeys[n * 256 + j];
    int pg[8];
#pragma unroll
    for (int g = 0; g < 8; g++) pg[g] = (int)((mk >> (35 - 5 * g)) & 31ull);

    // accumulate: acc[tp] = base-pair + sum_g S[g][pg[g]][t-pair]
    unsigned long long acc[TTILE / 2];
    const unsigned long long* basep = (const unsigned long long*)sbase;
#pragma unroll
    for (int tp = 0; tp < TTILE / 2; tp++) acc[tp] = basep[tp];

#pragma unroll
    for (int g = 0; g < 8; g++) {
        const unsigned long long* Srow = (const unsigned long long*)&S[g][pg[g]][0];
#pragma unroll
        for (int tp = 0; tp < TTILE / 2; tp++) {
            acc[tp] = add2(acc[tp], Srow[tp]);
        }
    }

    // coalesced stores (warp writes 32 consecutive j per t)
    float* outb = g_em + ((size_t)n * TT + t0) * 256 + j;
#pragma unroll
    for (int tp = 0; tp < TTILE / 2; tp++) {
        float v0, v1;
        up2(acc[tp], v0, v1);
        int te = 2 * tp, to = 2 * tp + 1;
        if (j == 0) { v0 = sblank[te]; v1 = sblank[to]; }
        if (t0 + te < TT) outb[(size_t)te * 256] = v0;
        if (t0 + to < TT) outb[(size_t)to * 256] = v1;
    }
}

// =====================================================================
// Kernel 3: CTC forward — 4 warps (one per SMSP), 3 pairs per thread.
// (unchanged from R11 — verified, 194us)
// =====================================================================
__device__ __forceinline__ float lg2_poly(float u) {   // lg2(1+u), u in [0,2]
    float x = u - 1.0f;
    float x2 = x * x;
    float p = fmaf(D5, x, D4);
    float q = fmaf(D3, x, D2);
    float r = fmaf(D1, x, D0);
    p = fmaf(p, x2, q);
    return fmaf(p, x2, r);
}

__device__ __forceinline__ void stage_rows4(float (*sEm)[256], const float* emn,
                                            int r0, int tid) {
#pragma unroll
    for (int i = 0; i < 4; i++) {
        int c = tid + i * 128;
        int r = r0 + (c >> 6);
        int off = (c & 63) * 4;
        if (r < TT) {
            uint32_t dst = (uint32_t)__cvta_generic_to_shared(&sEm[r & 31][off]);
            const float* src = emn + (size_t)r * 256 + off;
            asm volatile("cp.async.cg.shared.global [%0], [%1], 16;\n"
                         :: "r"(dst), "l"(src));
        }
    }
    asm volatile("cp.async.commit_group;\n" ::: "memory");
}

__global__ void __launch_bounds__(128) k_ctc(float* __restrict__ d_out) {
    const int n = blockIdx.x;
    const int tid = threadIdx.x;
    const int w = tid >> 5;
    const int l = tid & 31;
    const int qA = 72 * w + 3 * l;    // pairs qA, qA+1, qA+2
    const int qB = qA + 1;
    const int qC = qA + 2;

    __shared__ __align__(16) float sEm[32][256];
    __shared__ __align__(16) float  EX[2][4][8][6];
    __shared__ __align__(8)  float2 AF[256];

    const int tlen = g_tlen[n];
    const float* emn = g_em + (size_t)n * TT * 256;

    int labA = 0, labB = 0, labC = 0;
    float skipA = NEGF, skipB = NEGF, skipC = NEGF;
    if (qA < tlen) {
        labA = g_labels[n * 256 + qA];
        if (qA >= 1) {
            int lm = g_labels[n * 256 + qA - 1];
            if (labA != 0 && labA != lm) skipA = POSF;
        }
    }
    if (qB < tlen) {
        labB = g_labels[n * 256 + qB];
        int lm = g_labels[n * 256 + qB - 1];
        if (labB != 0 && labB != lm) skipB = POSF;
    }
    if (qC < tlen) {
        labC = g_labels[n * 256 + qC];
        int lm = g_labels[n * 256 + qC - 1];
        if (labC != 0 && labC != lm) skipC = POSF;
    }
    const float edge1 = (tid == 0) ? NEGF : POSF;

    float e0 = NEGF, o0 = NEGF, e1 = NEGF, o1 = NEGF, e2 = NEGF, o2 = NEGF;
    if (tid == 0) {
        e0 = __ldg(emn + 0);
        o0 = __ldg(emn + labA);
    }

    stage_rows4(sEm, emn, 1, tid);
    stage_rows4(sEm, emn, 9, tid);

#define DO_STEP(tt)                                                         \
    do {                                                                    \
        const float* srow = &sEm[(tt) & 31][0];                             \
        float emE = srow[0];                                                \
        float emA = srow[labA];                                             \
        float emB = srow[labB];                                             \
        float emC = srow[labC];                                             \
        float oPrev = __shfl_up_sync(0xffffffffu, o2, 1);                   \
        oPrev = fminf(oPrev, edge1);                                        \
        float o0o = o0, o1o = o1;                                           \
        float ccA = fminf(oPrev, skipA);                                    \
        float mEA = fmaxf(e0, oPrev);                                       \
        float dEA = fminf(e0, oPrev) - mEA;                                 \
        float hiA = fmaxf(o0, e0), loA = fminf(o0, e0);                     \
        float mOA = fmaxf(hiA, ccA);                                        \
        float seA = fminf(hiA, fmaxf(loA, ccA)) - mOA;                      \
        float thA = fminf(loA, ccA) - mOA;                                  \
        float ccB = fminf(o0o, skipB);                                      \
        float mEB = fmaxf(e1, o0o);                                         \
        float dEB = fminf(e1, o0o) - mEB;                                   \
        float hiB = fmaxf(o1, e1), loB = fminf(o1, e1);                     \
        float mOB = fmaxf(hiB, ccB);                                        \
        float seB = fminf(hiB, fmaxf(loB, ccB)) - mOB;                      \
        float thB = fminf(loB, ccB) - mOB;                                  \
        float ccC = fminf(o1o, skipC);                                      \
        float mEC = fmaxf(e2, o1o);                                         \
        float dEC = fminf(e2, o1o) - mEC;                                   \
        float hiC = fmaxf(o2, e2), loC = fminf(o2, e2);                     \
        float mOC = fmaxf(hiC, ccC);                                        \
        float seC = fminf(hiC, fmaxf(loC, ccC)) - mOC;                      \
        float thC = fminf(loC, ccC) - mOC;                                  \
        float uEA = ex2f(dEA);                                              \
        float uOA = 1.0f + ex2f(seA) + ex2f(thA);                           \
        float uEB = ex2f(dEB);                                              \
        float uOB = 1.0f + ex2f(seB) + ex2f(thB);                           \
        float uEC = ex2f(dEC);                                              \
        float uOC = 1.0f + ex2f(seC) + ex2f(thC);                           \
        e0 = (mEA + emE) + lg2_poly(uEA);                                   \
        o0 = (mOA + emA) + lg2f(uOA);                                       \
        e1 = (mEB + emE) + lg2_poly(uEB);                                   \
        o1 = (mOB + emB) + lg2f(uOB);                                       \
        e2 = (mEC + emE) + lg2_poly(uEC);                                   \
        o2 = (mOC + emC) + lg2f(uOC);                                       \
    } while (0)

    int buf = 0;
    for (int b = 0; b < 249; b++) {
        stage_rows4(sEm, emn, 8 * b + 17, tid);
        asm volatile("cp.async.wait_group 2;\n" ::: "memory");
        if (l >= 24) {
            float* ex = &EX[buf][w][l - 24][0];
            ex[0] = e0; ex[1] = o0; ex[2] = e1;
            ex[3] = o1; ex[4] = e2; ex[5] = o2;
        }
        __syncthreads();
        if (w > 0 && l < 8) {
            const float* ex = &EX[buf][w - 1][l][0];
            e0 = ex[0]; o0 = ex[1]; e1 = ex[2];
            o1 = ex[3]; e2 = ex[4]; o2 = ex[5];
        }
        buf ^= 1;

        const int t0 = 8 * b + 1;
#pragma unroll
        for (int s = 0; s < 8; s++) DO_STEP(t0 + s);
    }

    // tail: t = 1993..1999 (7 steps)
    {
        asm volatile("cp.async.wait_group 0;\n" ::: "memory");
        if (l >= 24) {
            float* ex = &EX[buf][w][l - 24][0];
            ex[0] = e0; ex[1] = o0; ex[2] = e1;
            ex[3] = o1; ex[4] = e2; ex[5] = o2;
        }
        __syncthreads();
        if (w > 0 && l < 8) {
            const float* ex = &EX[buf][w - 1][l][0];
            e0 = ex[0]; o0 = ex[1]; e1 = ex[2];
            o1 = ex[3]; e2 = ex[4]; o2 = ex[5];
        }
#pragma unroll
        for (int s = 0; s < 7; s++) DO_STEP(1993 + s);
    }
#undef DO_STEP

    // collect final alphas (valid lanes: warp0 all; others l >= 7)
    if (w == 0 || l >= 7) {
        if (qA < 256) AF[qA] = make_float2(e0, o0);
        if (qB < 256) AF[qB] = make_float2(e1, o1);
        if (qC < 256) AF[qC] = make_float2(e2, o2);
    }
    __syncthreads();

    if (tid == 0) {
        float ea = AF[tlen].x;
        float eb = AF[(tlen >= 1) ? tlen - 1 : 0].y;
        float m = fmaxf(ea, eb);
        float l2 = m + lg2f(ex2f(ea - m) + ex2f(eb - m));
        g_loss[n] = -l2 * LN2;
        __threadfence();
        unsigned int tk = atomicAdd(&g_done, 1u);
        if (tk == NB - 1) {
            __threadfence();
            volatile float* gl = g_loss;
            float s = 0.0f;
            for (int i = 0; i < NB; i++) s += gl[i];
            d_out[0] = s * (1.0f / (float)NB);
        }
    }
}

// =====================================================================
extern "C" void kernel_launch(void* const* d_in, const int* in_sizes, int n_in,
                              void* d_out, int out_size) {
    const float* lp = (const float*)d_in[0];
    const int*   tg = (const int*)d_in[1];
    if (n_in >= 2 && in_sizes[0] == NB * CH * LL) {
        lp = (const float*)d_in[1];
        tg = (const int*)d_in[0];
    }

    k_nop<<<1, 32>>>();
    k_preprocess<<<NB, 256>>>(tg);
    dim3 g2((TT + TTILE - 1) / TTILE, NB);
    k_emission<<<g2, 256>>>(lp);
    k_ctc<<<NB, 128>>>((float*)d_out);
}

// round 14
// speedup vs baseline: 1.0147x; 1.0147x over previous
#include <cuda_runtime.h>
#include <cstdint>
#include <cstddef>

#define CH   40
#define TT   2000
#define LL   256
#define NB   64
#define NEGF (-1.0e30f)
#define POSF (1.0e30f)
#define LOG2E 1.4426950408889634f
#define LN2   0.6931471805599453f

// lg2(1+u) ~ poly(x), x = u-1, u in [0,2]
#define D0 0.999835f
#define D1 0.721619f
#define D2 (-0.177414f)
#define D3 0.058070f
#define D4 (-0.029748f)
#define D5 0.0127536f

#define NTILE 63            // ceil(2000/32)
#define TTILE 32

// ---------------- device scratch ----------------
__device__ unsigned long long g_maskkeys[NB * 256];
__device__ int   g_labels[NB * 256];
__device__ int   g_tlen[NB];
__device__ float g_em[(size_t)NB * TT * 256];
__device__ float g_loss[NB];
__device__ unsigned int g_done;
__device__ unsigned int g_tileflag[NB * NTILE];

// ---------------- PTX helpers ----------------
__device__ __forceinline__ float ex2f(float x) {
    float r; asm("ex2.approx.ftz.f32 %0, %1;" : "=f"(r) : "f"(x)); return r;
}
__device__ __forceinline__ float lg2f(float x) {
    float r; asm("lg2.approx.ftz.f32 %0, %1;" : "=f"(r) : "f"(x)); return r;
}
__device__ __forceinline__ unsigned long long pk2(float x, float y) {
    unsigned long long r;
    asm("mov.b64 %0, {%1, %2};" : "=l"(r) : "f"(x), "f"(y));
    return r;
}
__device__ __forceinline__ void ffma2(unsigned long long &a, unsigned long long m, unsigned long long d) {
    asm("fma.rn.f32x2 %0, %1, %2, %3;" : "=l"(a) : "l"(m), "l"(d), "l"(a));
}
__device__ __forceinline__ void up2(unsigned long long v, float &x, float &y) {
    asm("mov.b64 {%0, %1}, %2;" : "=f"(x), "=f"(y) : "l"(v));
}

// =====================================================================
// Kernel 0: no-op (ncu capture index)
// =====================================================================
__global__ void k_nop() {}

// =====================================================================
// Kernel 1: preprocessing (verified exact) + flag reset
// =====================================================================
__global__ void k_preprocess(const int* __restrict__ targets) {
    const int n = blockIdx.x;
    const int l = threadIdx.x;

    __shared__ unsigned long long skey[256];
    __shared__ int sscan[256];
    __shared__ int sinv[256];

    if (n == 0 && l == 0) g_done = 0;
    if (l < NTILE) g_tileflag[n * NTILE + l] = 0u;

    unsigned long long key = 0ull;
#pragma unroll
    for (int c = 0; c < CH; c++) {
        key |= ((unsigned long long)(targets[(n * CH + c) * LL + l] & 1)) << (CH - 1 - c);
    }
    skey[l] = (key << 8) | (unsigned long long)l;
    __syncthreads();

    for (int k = 2; k <= 256; k <<= 1) {
        for (int j = k >> 1; j > 0; j >>= 1) {
            int ixj = l ^ j;
            if (ixj > l) {
                unsigned long long a = skey[l], b = skey[ixj];
                bool up = ((l & k) == 0);
                if ((a > b) == up) { skey[l] = b; skey[ixj] = a; }
            }
            __syncthreads();
        }
    }

    unsigned long long kv = skey[l] >> 8;
    unsigned long long kvp = (l > 0) ? (skey[l - 1] >> 8) : 0ull;
    int head = (l == 0 || kv != kvp) ? 1 : 0;
    sscan[l] = head;
    __syncthreads();
    for (int off = 1; off < 256; off <<= 1) {
        int v = sscan[l];
        int w = (l >= off) ? sscan[l - off] : 0;
        __syncthreads();
        sscan[l] = v + w;
        __syncthreads();
    }
    const int u   = sscan[255];
    const int uid = sscan[l] - 1;
    const int orig = (int)(skey[l] & 255ull);
    int inv2 = uid + 1; if (inv2 == u) inv2 = 0;
    sinv[orig] = inv2;
    if (head) g_maskkeys[n * 256 + inv2] = kv;
    __syncthreads();

    int flag = (l > 0 && sinv[l] != sinv[l - 1]) ? 1 : 0;
    int myinv = sinv[l];
    sscan[l] = flag;
    __syncthreads();
    for (int off = 1; off < 256; off <<= 1) {
        int v = sscan[l];
        int w = (l >= off) ? sscan[l - off] : 0;
        __syncthreads();
        sscan[l] = v + w;
        __syncthreads();
    }
    if (flag) g_labels[n * 256 + (sscan[l] - 1)] = myinv;
    if (l == 0) g_tlen[n] = sscan[255];
}

// =====================================================================
// Shared-memory union for the fused kernel
// =====================================================================
struct CtcS {
    float sEm[32][256];        // 32 KB
    float EX[2][4][8][6];      // 1.5 KB
    float2 AF[256];            // 2 KB
};
struct EmS {
    float d2f[CH][TTILE];
    float sbase[TTILE];
    float sblank[TTILE];
};
#define SMBUF_BYTES (sizeof(CtcS) > sizeof(EmS) ? sizeof(CtcS) : sizeof(EmS))

// =====================================================================
// Emission body (v3, verified): 128 threads, 2 j-columns per thread.
// Signals g_tileflag[n][bt] when its tile is globally visible.
// =====================================================================
__device__ __forceinline__ void emission_block(int bt, int n,
                                               const float* __restrict__ lp,
                                               char* smraw) {
    EmS* sm = (EmS*)smraw;
    const int t0 = bt * TTILE;
    const int j0 = threadIdx.x;
    const int j1 = j0 + 128;

    const float* lp0 = lp + ((size_t)n * 2 + 0) * CH * TT;
    const float* lp1 = lp + ((size_t)n * 2 + 1) * CH * TT;

#pragma unroll
    for (int it = 0; it < 10; it++) {
        int idx = it * 128 + j0;
        int c = idx >> 5;
        int tt = idx & 31;
        int t = t0 + tt;
        float v = 0.0f;
        if (t < TT) {
            float x0 = __ldg(lp0 + c * TT + t);
            float x1 = __ldg(lp1 + c * TT + t);
            v = (x1 - x0) * LOG2E;
        }
        sm->d2f[c][tt] = v;
    }
    if (j0 < TTILE) {
        int t = t0 + j0;
        float b = 0.0f, bl = 0.0f;
        if (t < TT) {
#pragma unroll
            for (int c = 0; c < CH; c++) b += __ldg(lp0 + c * TT + t);
            bl = __ldg(lp1 + t);
        }
        sm->sbase[j0]  = b * LOG2E;
        sm->sblank[j0] = bl * LOG2E;
    }
    __syncthreads();

    const unsigned long long mk0 = g_maskkeys[n * 256 + j0];
    const unsigned long long mk1 = g_maskkeys[n * 256 + j1];

    unsigned long long acc0[TTILE / 2], acc1[TTILE / 2];
    const unsigned long long* basep = (const unsigned long long*)sm->sbase;
#pragma unroll
    for (int tp = 0; tp < TTILE / 2; tp++) { acc0[tp] = basep[tp]; acc1[tp] = basep[tp]; }

#pragma unroll 8
    for (int c = 0; c < CH; c++) {
        float m0 = (float)((mk0 >> (CH - 1 - c)) & 1ull);
        float m1 = (float)((mk1 >> (CH - 1 - c)) & 1ull);
        unsigned long long mm0 = pk2(m0, m0);
        unsigned long long mm1 = pk2(m1, m1);
        const ulonglong2* drow = (const ulonglong2*)&sm->d2f[c][0];
#pragma unroll
        for (int tq = 0; tq < TTILE / 4; tq++) {
            ulonglong2 d = drow[tq];
            ffma2(acc0[2 * tq],     mm0, d.x);
            ffma2(acc0[2 * tq + 1], mm0, d.y);
            ffma2(acc1[2 * tq],     mm1, d.x);
            ffma2(acc1[2 * tq + 1], mm1, d.y);
        }
    }

    float* outb0 = g_em + ((size_t)n * TT + t0) * 256 + j0;
    float* outb1 = g_em + ((size_t)n * TT + t0) * 256 + j1;
#pragma unroll
    for (int tp = 0; tp < TTILE / 2; tp++) {
        int te = 2 * tp, to = 2 * tp + 1;
        float v0, v1;
        up2(acc0[tp], v0, v1);
        if (j0 == 0) { v0 = sm->sblank[te]; v1 = sm->sblank[to]; }
        if (t0 + te < TT) outb0[(size_t)te * 256] = v0;
        if (t0 + to < TT) outb0[(size_t)to * 256] = v1;
        float w0, w1;
        up2(acc1[tp], w0, w1);
        if (t0 + te < TT) outb1[(size_t)te * 256] = w0;
        if (t0 + to < TT) outb1[(size_t)to * 256] = w1;
    }

    // release: all stores visible at GPU scope, then set flag
    __threadfence();
    __syncthreads();
    if (threadIdx.x == 0) atomicExch(&g_tileflag[n * NTILE + bt], 1u);
}

// =====================================================================
// CTC body (R11, verified): 4 warps, 3 pairs/thread, halo windows,
// now gated on g_tileflag before each tile crossing.
// =====================================================================
__device__ __forceinline__ float lg2_poly(float u) {
    float x = u - 1.0f;
    float x2 = x * x;
    float p = fmaf(D5, x, D4);
    float q = fmaf(D3, x, D2);
    float r = fmaf(D1, x, D0);
    p = fmaf(p, x2, q);
    return fmaf(p, x2, r);
}

__device__ __forceinline__ void stage_rows4(float (*sEm)[256], const float* emn,
                                            int r0, int tid) {
#pragma unroll
    for (int i = 0; i < 4; i++) {
        int c = tid + i * 128;
        int r = r0 + (c >> 6);
        int off = (c & 63) * 4;
        if (r < TT) {
            uint32_t dst = (uint32_t)__cvta_generic_to_shared(&sEm[r & 31][off]);
            const float* src = emn + (size_t)r * 256 + off;
            asm volatile("cp.async.cg.shared.global [%0], [%1], 16;\n"
                         :: "r"(dst), "l"(src));
        }
    }
    asm volatile("cp.async.commit_group;\n" ::: "memory");
}

__device__ __forceinline__ void tile_wait(int n, int tile, int tid) {
    if (tid == 0) {
        volatile unsigned int* f = &g_tileflag[n * NTILE + tile];
        while (*f == 0u) __nanosleep(64);
        __threadfence();
    }
    __syncthreads();
}

__device__ __forceinline__ void ctc_block(int n, float* __restrict__ d_out,
                                          char* smraw) {
    CtcS* sm = (CtcS*)smraw;
    const int tid = threadIdx.x;
    const int w = tid >> 5;
    const int l = tid & 31;
    const int qA = 72 * w + 3 * l;
    const int qB = qA + 1;
    const int qC = qA + 2;

    const int tlen = g_tlen[n];
    const float* emn = g_em + (size_t)n * TT * 256;

    int labA = 0, labB = 0, labC = 0;
    float skipA = NEGF, skipB = NEGF, skipC = NEGF;
    if (qA < tlen) {
        labA = g_labels[n * 256 + qA];
        if (qA >= 1) {
            int lm = g_labels[n * 256 + qA - 1];
            if (labA != 0 && labA != lm) skipA = POSF;
        }
    }
    if (qB < tlen) {
        labB = g_labels[n * 256 + qB];
        int lm = g_labels[n * 256 + qB - 1];
        if (labB != 0 && labB != lm) skipB = POSF;
    }
    if (qC < tlen) {
        labC = g_labels[n * 256 + qC];
        int lm = g_labels[n * 256 + qC - 1];
        if (labC != 0 && labC != lm) skipC = POSF;
    }
    const float edge1 = (tid == 0) ? NEGF : POSF;

    // wait for tile 0 (rows 0..31) before any g_em access
    tile_wait(n, 0, tid);

    float e0 = NEGF, o0 = NEGF, e1 = NEGF, o1 = NEGF, e2 = NEGF, o2 = NEGF;
    if (tid == 0) {
        e0 = __ldg(emn + 0);
        o0 = __ldg(emn + labA);
    }

    stage_rows4(sm->sEm, emn, 1, tid);
    stage_rows4(sm->sEm, emn, 9, tid);

#define DO_STEP(tt)                                                         \
    do {                                                                    \
        const float* srow = &sm->sEm[(tt) & 31][0];                         \
        float emE = srow[0];                                                \
        float emA = srow[labA];                                             \
        float emB = srow[labB];                                             \
        float emC = srow[labC];                                             \
        float oPrev = __shfl_up_sync(0xffffffffu, o2, 1);                   \
        oPrev = fminf(oPrev, edge1);                                        \
        float o0o = o0, o1o = o1;                                           \
        float ccA = fminf(oPrev, skipA);                                    \
        float mEA = fmaxf(e0, oPrev);                                       \
        float dEA = fminf(e0, oPrev) - mEA;                                 \
        float hiA = fmaxf(o0, e0), loA = fminf(o0, e0);                     \
        float mOA = fmaxf(hiA, ccA);                                        \
        float seA = fminf(hiA, fmaxf(loA, ccA)) - mOA;                      \
        float thA = fminf(loA, ccA) - mOA;                                  \
        float ccB = fminf(o0o, skipB);                                      \
        float mEB = fmaxf(e1, o0o);                                         \
        float dEB = fminf(e1, o0o) - mEB;                                   \
        float hiB = fmaxf(o1, e1), loB = fminf(o1, e1);                     \
        float mOB = fmaxf(hiB, ccB);                                        \
        float seB = fminf(hiB, fmaxf(loB, ccB)) - mOB;                      \
        float thB = fminf(loB, ccB) - mOB;                                  \
        float ccC = fminf(o1o, skipC);                                      \
        float mEC = fmaxf(e2, o1o);                                         \
        float dEC = fminf(e2, o1o) - mEC;                                   \
        float hiC = fmaxf(o2, e2), loC = fminf(o2, e2);                     \
        float mOC = fmaxf(hiC, ccC);                                        \
        float seC = fminf(hiC, fmaxf(loC, ccC)) - mOC;                      \
        float thC = fminf(loC, ccC) - mOC;                                  \
        float uEA = ex2f(dEA);                                              \
        float uOA = 1.0f + ex2f(seA) + ex2f(thA);                           \
        float uEB = ex2f(dEB);                                              \
        float uOB = 1.0f + ex2f(seB) + ex2f(thB);                           \
        float uEC = ex2f(dEC);                                              \
        float uOC = 1.0f + ex2f(seC) + ex2f(thC);                           \
        e0 = (mEA + emE) + lg2_poly(uEA);                                   \
        o0 = (mOA + emA) + lg2f(uOA);                                       \
        e1 = (mEB + emE) + lg2_poly(uEB);                                   \
        o1 = (mOB + emB) + lg2f(uOB);                                       \
        e2 = (mEC + emE) + lg2_poly(uEC);                                   \
        o2 = (mOC + emC) + lg2f(uOC);                                       \
    } while (0)

    int buf = 0;
    int last_tile = 0;
    for (int b = 0; b < 249; b++) {
        // gate on the tile containing the rows staged this window
        int tn = (8 * b + 24) >> 5;
        if (tn > NTILE - 1) tn = NTILE - 1;
        if (tn != last_tile) {
            tile_wait(n, tn, tid);
            last_tile = tn;
        }

        stage_rows4(sm->sEm, emn, 8 * b + 17, tid);
        asm volatile("cp.async.wait_group 2;\n" ::: "memory");
        if (l >= 24) {
            float* ex = &sm->EX[buf][w][l - 24][0];
            ex[0] = e0; ex[1] = o0; ex[2] = e1;
            ex[3] = o1; ex[4] = e2; ex[5] = o2;
        }
        __syncthreads();
        if (w > 0 && l < 8) {
            const float* ex = &sm->EX[buf][w - 1][l][0];
            e0 = ex[0]; o0 = ex[1]; e1 = ex[2];
            o1 = ex[3]; e2 = ex[4]; o2 = ex[5];
        }
        buf ^= 1;

        const int t0 = 8 * b + 1;
#pragma unroll
        for (int s = 0; s < 8; s++) DO_STEP(t0 + s);
    }

    // tail: t = 1993..1999
    {
        asm volatile("cp.async.wait_group 0;\n" ::: "memory");
        if (l >= 24) {
            float* ex = &sm->EX[buf][w][l - 24][0];
            ex[0] = e0; ex[1] = o0; ex[2] = e1;
            ex[3] = o1; ex[4] = e2; ex[5] = o2;
        }
        __syncthreads();
        if (w > 0 && l < 8) {
            const float* ex = &sm->EX[buf][w - 1][l][0];
            e0 = ex[0]; o0 = ex[1]; e1 = ex[2];
            o1 = ex[3]; e2 = ex[4]; o2 = ex[5];
        }
#pragma unroll
        for (int s = 0; s < 7; s++) DO_STEP(1993 + s);
    }
#undef DO_STEP

    if (w == 0 || l >= 7) {
        if (qA < 256) sm->AF[qA] = make_float2(e0, o0);
        if (qB < 256) sm->AF[qB] = make_float2(e1, o1);
        if (qC < 256) sm->AF[qC] = make_float2(e2, o2);
    }
    __syncthreads();

    if (tid == 0) {
        float ea = sm->AF[tlen].x;
        float eb = sm->AF[(tlen >= 1) ? tlen - 1 : 0].y;
        float m = fmaxf(ea, eb);
        float l2 = m + lg2f(ex2f(ea - m) + ex2f(eb - m));
        g_loss[n] = -l2 * LN2;
        __threadfence();
        unsigned int tk = atomicAdd(&g_done, 1u);
        if (tk == NB - 1) {
            __threadfence();
            volatile float* gl = g_loss;
            float s = 0.0f;
            for (int i = 0; i < NB; i++) s += gl[i];
            d_out[0] = s * (1.0f / (float)NB);
        }
    }
}

// =====================================================================
// Fused kernel: blocks [0, 64) run CTC; blocks [64, 4096) run emission.
// =====================================================================
__global__ void __launch_bounds__(128) k_fused(const float* __restrict__ lp,
                                               float* __restrict__ d_out) {
    __shared__ __align__(16) char smbuf[SMBUF_BYTES];
    if (blockIdx.x < NB) {
        ctc_block(blockIdx.x, d_out, smbuf);
    } else {
        int eb = blockIdx.x - NB;
        emission_block(eb >> 6, eb & 63, lp, smbuf);
    }
}

// =====================================================================
extern "C" void kernel_launch(void* const* d_in, const int* in_sizes, int n_in,
                              void* d_out, int out_size) {
    const float* lp = (const float*)d_in[0];
    const int*   tg = (const int*)d_in[1];
    if (n_in >= 2 && in_sizes[0] == NB * CH * LL) {
        lp = (const float*)d_in[1];
        tg = (const int*)d_in[0];
    }

    k_nop<<<1, 32>>>();
    k_preprocess<<<NB, 256>>>(tg);
    k_fused<<<NB + NTILE * 64, 128>>>(lp, (float*)d_out);
}

// round 15
// speedup vs baseline: 1.0388x; 1.0238x over previous
#include <cuda_runtime.h>
#include <cstdint>
#include <cstddef>

#define CH   40
#define TT   2000
#define LL   256
#define NB   64
#define NEGF (-1.0e30f)
#define POSF (1.0e30f)
#define LOG2E 1.4426950408889634f
#define LN2   0.6931471805599453f

#define D0 0.999835f
#define D1 0.721619f
#define D2 (-0.177414f)
#define D3 0.058070f
#define D4 (-0.029748f)
#define D5 0.0127536f

#define NTILE 63            // ceil(2000/32)
#define TTILE 32
#define EMB   84            // emission blocks
#define NWORK (EMB * 6)     // 504 emission workers
#define NUNIT (NTILE * NB)  // 4032 = 504 * 8

// ---------------- device scratch ----------------
__device__ unsigned long long g_maskkeys[NB * 256];
__device__ int   g_labels[NB * 256];
__device__ int   g_tlen[NB];
__device__ float g_em[(size_t)NB * TT * 256];
__device__ float g_loss[NB];
__device__ unsigned int g_done;
__device__ unsigned int g_tileflag[NB * NTILE];

// ---------------- PTX helpers ----------------
__device__ __forceinline__ float ex2f(float x) {
    float r; asm("ex2.approx.ftz.f32 %0, %1;" : "=f"(r) : "f"(x)); return r;
}
__device__ __forceinline__ float lg2f(float x) {
    float r; asm("lg2.approx.ftz.f32 %0, %1;" : "=f"(r) : "f"(x)); return r;
}
__device__ __forceinline__ unsigned long long pk2(float x, float y) {
    unsigned long long r;
    asm("mov.b64 %0, {%1, %2};" : "=l"(r) : "f"(x), "f"(y));
    return r;
}
__device__ __forceinline__ void ffma2(unsigned long long &a, unsigned long long m, unsigned long long d) {
    asm("fma.rn.f32x2 %0, %1, %2, %3;" : "=l"(a) : "l"(m), "l"(d), "l"(a));
}
__device__ __forceinline__ void up2(unsigned long long v, float &x, float &y) {
    asm("mov.b64 {%0, %1}, %2;" : "=f"(x), "=f"(y) : "l"(v));
}
// named barrier: 128 threads, id 1..7
__device__ __forceinline__ void barx(int id) {
    asm volatile("bar.sync %0, 128;" :: "r"(id) : "memory");
}

// =====================================================================
// Kernel 0: no-op (ncu capture index alignment)
// =====================================================================
__global__ void k_nop() {}

// =====================================================================
// Kernel 1: preprocessing (verified exact) + flag reset
// =====================================================================
__global__ void k_preprocess(const int* __restrict__ targets) {
    const int n = blockIdx.x;
    const int l = threadIdx.x;

    __shared__ unsigned long long skey[256];
    __shared__ int sscan[256];
    __shared__ int sinv[256];

    if (n == 0 && l == 0) g_done = 0;
    if (l < NTILE) g_tileflag[n * NTILE + l] = 0u;

    unsigned long long key = 0ull;
#pragma unroll
    for (int c = 0; c < CH; c++) {
        key |= ((unsigned long long)(targets[(n * CH + c) * LL + l] & 1)) << (CH - 1 - c);
    }
    skey[l] = (key << 8) | (unsigned long long)l;
    __syncthreads();

    for (int k = 2; k <= 256; k <<= 1) {
        for (int j = k >> 1; j > 0; j >>= 1) {
            int ixj = l ^ j;
            if (ixj > l) {
                unsigned long long a = skey[l], b = skey[ixj];
                bool up = ((l & k) == 0);
                if ((a > b) == up) { skey[l] = b; skey[ixj] = a; }
            }
            __syncthreads();
        }
    }

    unsigned long long kv = skey[l] >> 8;
    unsigned long long kvp = (l > 0) ? (skey[l - 1] >> 8) : 0ull;
    int head = (l == 0 || kv != kvp) ? 1 : 0;
    sscan[l] = head;
    __syncthreads();
    for (int off = 1; off < 256; off <<= 1) {
        int v = sscan[l];
        int w = (l >= off) ? sscan[l - off] : 0;
        __syncthreads();
        sscan[l] = v + w;
        __syncthreads();
    }
    const int u   = sscan[255];
    const int uid = sscan[l] - 1;
    const int orig = (int)(skey[l] & 255ull);
    int inv2 = uid + 1; if (inv2 == u) inv2 = 0;
    sinv[orig] = inv2;
    if (head) g_maskkeys[n * 256 + inv2] = kv;
    __syncthreads();

    int flag = (l > 0 && sinv[l] != sinv[l - 1]) ? 1 : 0;
    int myinv = sinv[l];
    sscan[l] = flag;
    __syncthreads();
    for (int off = 1; off < 256; off <<= 1) {
        int v = sscan[l];
        int w = (l >= off) ? sscan[l - off] : 0;
        __syncthreads();
        sscan[l] = v + w;
        __syncthreads();
    }
    if (flag) g_labels[n * 256 + (sscan[l] - 1)] = myinv;
    if (l == 0) g_tlen[n] = sscan[255];
}

// =====================================================================
// Shared-memory union
// =====================================================================
struct CtcS {
    float sEm[32][256];        // 32 KB
    float EX[2][4][8][6];      // 1.5 KB
    float2 AF[256];            // 2 KB
};
struct EmS {
    float d2f[CH][TTILE];
    float sbase[TTILE];
    float sblank[TTILE];
};
union SmU {
    CtcS ctc;
    EmS  em[6];
};

// =====================================================================
// Emission unit (v3 body, verified), 128-thread group, named barrier.
// =====================================================================
__device__ __forceinline__ void emission_unit(int bt, int n,
                                              const float* __restrict__ lp,
                                              EmS* sm, int ltid, int barid) {
    const int t0 = bt * TTILE;
    const int j0 = ltid;
    const int j1 = j0 + 128;

    const float* lp0 = lp + ((size_t)n * 2 + 0) * CH * TT;
    const float* lp1 = lp + ((size_t)n * 2 + 1) * CH * TT;

#pragma unroll
    for (int it = 0; it < 10; it++) {
        int idx = it * 128 + j0;
        int c = idx >> 5;
        int tt = idx & 31;
        int t = t0 + tt;
        float v = 0.0f;
        if (t < TT) {
            float x0 = __ldg(lp0 + c * TT + t);
            float x1 = __ldg(lp1 + c * TT + t);
            v = (x1 - x0) * LOG2E;
        }
        sm->d2f[c][tt] = v;
    }
    if (j0 < TTILE) {
        int t = t0 + j0;
        float b = 0.0f, bl = 0.0f;
        if (t < TT) {
#pragma unroll
            for (int c = 0; c < CH; c++) b += __ldg(lp0 + c * TT + t);
            bl = __ldg(lp1 + t);
        }
        sm->sbase[j0]  = b * LOG2E;
        sm->sblank[j0] = bl * LOG2E;
    }
    barx(barid);

    const unsigned long long mk0 = g_maskkeys[n * 256 + j0];
    const unsigned long long mk1 = g_maskkeys[n * 256 + j1];

    unsigned long long acc0[TTILE / 2], acc1[TTILE / 2];
    const unsigned long long* basep = (const unsigned long long*)sm->sbase;
#pragma unroll
    for (int tp = 0; tp < TTILE / 2; tp++) { acc0[tp] = basep[tp]; acc1[tp] = basep[tp]; }

#pragma unroll 8
    for (int c = 0; c < CH; c++) {
        float m0 = (float)((mk0 >> (CH - 1 - c)) & 1ull);
        float m1 = (float)((mk1 >> (CH - 1 - c)) & 1ull);
        unsigned long long mm0 = pk2(m0, m0);
        unsigned long long mm1 = pk2(m1, m1);
        const ulonglong2* drow = (const ulonglong2*)&sm->d2f[c][0];
#pragma unroll
        for (int tq = 0; tq < TTILE / 4; tq++) {
            ulonglong2 d = drow[tq];
            ffma2(acc0[2 * tq],     mm0, d.x);
            ffma2(acc0[2 * tq + 1], mm0, d.y);
            ffma2(acc1[2 * tq],     mm1, d.x);
            ffma2(acc1[2 * tq + 1], mm1, d.y);
        }
    }

    float* outb0 = g_em + ((size_t)n * TT + t0) * 256 + j0;
    float* outb1 = g_em + ((size_t)n * TT + t0) * 256 + j1;
#pragma unroll
    for (int tp = 0; tp < TTILE / 2; tp++) {
        int te = 2 * tp, to = 2 * tp + 1;
        float v0, v1;
        up2(acc0[tp], v0, v1);
        if (j0 == 0) { v0 = sm->sblank[te]; v1 = sm->sblank[to]; }
        if (t0 + te < TT) outb0[(size_t)te * 256] = v0;
        if (t0 + to < TT) outb0[(size_t)to * 256] = v1;
        float w0, w1;
        up2(acc1[tp], w0, w1);
        if (t0 + te < TT) outb1[(size_t)te * 256] = w0;
        if (t0 + to < TT) outb1[(size_t)to * 256] = w1;
    }

    __threadfence();
    barx(barid);                 // all stores issued+fenced before flag
    if (ltid == 0) atomicExch(&g_tileflag[n * NTILE + bt], 1u);
}

// =====================================================================
// CTC body (R11, verified) with named barrier + tile gating
// =====================================================================
__device__ __forceinline__ float lg2_poly(float u) {
    float x = u - 1.0f;
    float x2 = x * x;
    float p = fmaf(D5, x, D4);
    float q = fmaf(D3, x, D2);
    float r = fmaf(D1, x, D0);
    p = fmaf(p, x2, q);
    return fmaf(p, x2, r);
}

__device__ __forceinline__ void stage_rows4(float (*sEm)[256], const float* emn,
                                            int r0, int tid) {
#pragma unroll
    for (int i = 0; i < 4; i++) {
        int c = tid + i * 128;
        int r = r0 + (c >> 6);
        int off = (c & 63) * 4;
        if (r < TT) {
            uint32_t dst = (uint32_t)__cvta_generic_to_shared(&sEm[r & 31][off]);
            const float* src = emn + (size_t)r * 256 + off;
            asm volatile("cp.async.cg.shared.global [%0], [%1], 16;\n"
                         :: "r"(dst), "l"(src));
        }
    }
    asm volatile("cp.async.commit_group;\n" ::: "memory");
}

__device__ __forceinline__ void tile_wait(int n, int tile, int tid) {
    if (tid == 0) {
        volatile unsigned int* f = &g_tileflag[n * NTILE + tile];
        while (*f == 0u) __nanosleep(64);
        __threadfence();
    }
    barx(1);
}

__device__ __forceinline__ void ctc_block(int n, float* __restrict__ d_out,
                                          CtcS* sm) {
    const int tid = threadIdx.x;      // 0..127 (others exited)
    const int w = tid >> 5;
    const int l = tid & 31;
    const int qA = 72 * w + 3 * l;
    const int qB = qA + 1;
    const int qC = qA + 2;

    const int tlen = g_tlen[n];
    const float* emn = g_em + (size_t)n * TT * 256;

    int labA = 0, labB = 0, labC = 0;
    float skipA = NEGF, skipB = NEGF, skipC = NEGF;
    if (qA < tlen) {
        labA = g_labels[n * 256 + qA];
        if (qA >= 1) {
            int lm = g_labels[n * 256 + qA - 1];
            if (labA != 0 && labA != lm) skipA = POSF;
        }
    }
    if (qB < tlen) {
        labB = g_labels[n * 256 + qB];
        int lm = g_labels[n * 256 + qB - 1];
        if (labB != 0 && labB != lm) skipB = POSF;
    }
    if (qC < tlen) {
        labC = g_labels[n * 256 + qC];
        int lm = g_labels[n * 256 + qC - 1];
        if (labC != 0 && labC != lm) skipC = POSF;
    }
    const float edge1 = (tid == 0) ? NEGF : POSF;

    tile_wait(n, 0, tid);

    float e0 = NEGF, o0 = NEGF, e1 = NEGF, o1 = NEGF, e2 = NEGF, o2 = NEGF;
    if (tid == 0) {
        e0 = __ldg(emn + 0);
        o0 = __ldg(emn + labA);
    }

    stage_rows4(sm->sEm, emn, 1, tid);
    stage_rows4(sm->sEm, emn, 9, tid);

#define DO_STEP(tt)                                                         \
    do {                                                                    \
        const float* srow = &sm->sEm[(tt) & 31][0];                         \
        float emE = srow[0];                                                \
        float emA = srow[labA];                                             \
        float emB = srow[labB];                                             \
        float emC = srow[labC];                                             \
        float oPrev = __shfl_up_sync(0xffffffffu, o2, 1);                   \
        oPrev = fminf(oPrev, edge1);                                        \
        float o0o = o0, o1o = o1;                                           \
        float ccA = fminf(oPrev, skipA);                                    \
        float mEA = fmaxf(e0, oPrev);                                       \
        float dEA = fminf(e0, oPrev) - mEA;                                 \
        float hiA = fmaxf(o0, e0), loA = fminf(o0, e0);                     \
        float mOA = fmaxf(hiA, ccA);                                        \
        float seA = fminf(hiA, fmaxf(loA, ccA)) - mOA;                      \
        float thA = fminf(loA, ccA) - mOA;                                  \
        float ccB = fminf(o0o, skipB);                                      \
        float mEB = fmaxf(e1, o0o);                                         \
        float dEB = fminf(e1, o0o) - mEB;                                   \
        float hiB = fmaxf(o1, e1), loB = fminf(o1, e1);                     \
        float mOB = fmaxf(hiB, ccB);                                        \
        float seB = fminf(hiB, fmaxf(loB, ccB)) - mOB;                      \
        float thB = fminf(loB, ccB) - mOB;                                  \
        float ccC = fminf(o1o, skipC);                                      \
        float mEC = fmaxf(e2, o1o);                                         \
        float dEC = fminf(e2, o1o) - mEC;                                   \
        float hiC = fmaxf(o2, e2), loC = fminf(o2, e2);                     \
        float mOC = fmaxf(hiC, ccC);                                        \
        float seC = fminf(hiC, fmaxf(loC, ccC)) - mOC;                      \
        float thC = fminf(loC, ccC) - mOC;                                  \
        float uEA = ex2f(dEA);                                              \
        float uOA = 1.0f + ex2f(seA) + ex2f(thA);                           \
        float uEB = ex2f(dEB);                                              \
        float uOB = 1.0f + ex2f(seB) + ex2f(thB);                           \
        float uEC = ex2f(dEC);                                              \
        float uOC = 1.0f + ex2f(seC) + ex2f(thC);                           \
        e0 = (mEA + emE) + lg2_poly(uEA);                                   \
        o0 = (mOA + emA) + lg2f(uOA);                                       \
        e1 = (mEB + emE) + lg2_poly(uEB);                                   \
        o1 = (mOB + emB) + lg2f(uOB);                                       \
        e2 = (mEC + emE) + lg2_poly(uEC);                                   \
        o2 = (mOC + emC) + lg2f(uOC);                                       \
    } while (0)

    int buf = 0;
    int last_tile = 0;
    for (int b = 0; b < 249; b++) {
        int tn = (8 * b + 24) >> 5;
        if (tn > NTILE - 1) tn = NTILE - 1;
        if (tn != last_tile) {
            tile_wait(n, tn, tid);
            last_tile = tn;
        }

        stage_rows4(sm->sEm, emn, 8 * b + 17, tid);
        asm volatile("cp.async.wait_group 2;\n" ::: "memory");
        if (l >= 24) {
            float* ex = &sm->EX[buf][w][l - 24][0];
            ex[0] = e0; ex[1] = o0; ex[2] = e1;
            ex[3] = o1; ex[4] = e2; ex[5] = o2;
        }
        barx(1);
        if (w > 0 && l < 8) {
            const float* ex = &sm->EX[buf][w - 1][l][0];
            e0 = ex[0]; o0 = ex[1]; e1 = ex[2];
            o1 = ex[3]; e2 = ex[4]; o2 = ex[5];
        }
        buf ^= 1;

        const int t0 = 8 * b + 1;
#pragma unroll
        for (int s = 0; s < 8; s++) DO_STEP(t0 + s);
    }

    {
        asm volatile("cp.async.wait_group 0;\n" ::: "memory");
        if (l >= 24) {
            float* ex = &sm->EX[buf][w][l - 24][0];
            ex[0] = e0; ex[1] = o0; ex[2] = e1;
            ex[3] = o1; ex[4] = e2; ex[5] = o2;
        }
        barx(1);
        if (w > 0 && l < 8) {
            const float* ex = &sm->EX[buf][w - 1][l][0];
            e0 = ex[0]; o0 = ex[1]; e1 = ex[2];
            o1 = ex[3]; e2 = ex[4]; o2 = ex[5];
        }
#pragma unroll
        for (int s = 0; s < 7; s++) DO_STEP(1993 + s);
    }
#undef DO_STEP

    if (w == 0 || l >= 7) {
        if (qA < 256) sm->AF[qA] = make_float2(e0, o0);
        if (qB < 256) sm->AF[qB] = make_float2(e1, o1);
        if (qC < 256) sm->AF[qC] = make_float2(e2, o2);
    }
    barx(1);

    if (tid == 0) {
        float ea = sm->AF[tlen].x;
        float eb = sm->AF[(tlen >= 1) ? tlen - 1 : 0].y;
        float m = fmaxf(ea, eb);
        float l2 = m + lg2f(ex2f(ea - m) + ex2f(eb - m));
        g_loss[n] = -l2 * LN2;
        __threadfence();
        unsigned int tk = atomicAdd(&g_done, 1u);
        if (tk == NB - 1) {
            __threadfence();
            volatile float* gl = g_loss;
            float s = 0.0f;
            for (int i = 0; i < NB; i++) s += gl[i];
            d_out[0] = s * (1.0f / (float)NB);
        }
    }
}

// =====================================================================
// Fused persistent kernel: 148 blocks x 768 threads, 1 block/SM
// (reg-limited). Blocks [0,64): ctc on threads 0..127. Blocks [64,148):
// 6 independent emission workers of 128 threads each.
// =====================================================================
__global__ void __launch_bounds__(768, 1) k_fused(const float* __restrict__ lp,
                                                  float* __restrict__ d_out) {
    __shared__ __align__(16) SmU smu;

    if (blockIdx.x < NB) {
        if (threadIdx.x < 128) ctc_block(blockIdx.x, d_out, &smu.ctc);
        // threads 128..767 exit
    } else {
        int eb  = blockIdx.x - NB;          // 0..83
        int grp = threadIdx.x >> 7;         // 0..5
        int ltid = threadIdx.x & 127;
        int worker = eb * 6 + grp;          // 0..503
        EmS* sm = &smu.em[grp];
#pragma unroll 1
        for (int r = 0; r < NUNIT / NWORK; r++) {
            int u = worker + r * NWORK;     // ascending tiles
            emission_unit(u >> 6, u & 63, lp, sm, ltid, 2 + grp);
        }
    }
}

// =====================================================================
extern "C" void kernel_launch(void* const* d_in, const int* in_sizes, int n_in,
                              void* d_out, int out_size) {
    const float* lp = (const float*)d_in[0];
    const int*   tg = (const int*)d_in[1];
    if (n_in >= 2 && in_sizes[0] == NB * CH * LL) {
        lp = (const float*)d_in[1];
        tg = (const int*)d_in[0];
    }

    k_nop<<<1, 32>>>();
    k_nop<<<1, 32>>>();
    k_preprocess<<<NB, 256>>>(tg);
    k_fused<<<NB + EMB, 768>>>(lp, (float*)d_out);
}